// round 12
// baseline (speedup 1.0000x reference)
#include <cuda_runtime.h>
#include <cstddef>

#define NE 1600000
#define NV 100000
#define NLAYER 20
#define BN_EPS 1e-5f
#define NT 256
#define NBLK2 3125              // NE/2 / 256 exactly -> no bounds checks
#define NBLK4 1563              // ceil(NE/4 / 256) for head
#define NBLKI 391               // ceil(NV / 256) for init

#define GDC_WAIT   asm volatile("griddepcontrol.wait;" ::: "memory")
#define GDC_LAUNCH asm volatile("griddepcontrol.launch_dependents;" ::: "memory")

// ---------------- constant weights ----------------
struct CW {
    float we_w1[36], we_b1[4], we_g1[4], we_be1[4], we_w2[12], we_b2[3];
    float wv_w1[18], wv_b1[3], wv_g1[3], wv_be1[3], wv_w2[9], wv_b2[3];
    float ow1[9], ob1[3], og[3], obe[3], ow2[6], ob2[2];
};
__constant__ CW cw;

// ---------------- persistent device state ----------------
__device__ float4 g_M[2][NV];     // node features, double buffered
__device__ float  g_H[NE * 3];    // edge features
__device__ float4 g_Y[NE];        // phase-A pre-BN e-MLP output
__device__ float  g_Z[NE * 3];    // phase-A: mi-part of z ; phase-B: full z
__device__ float  g_stats[22 * 16];

__device__ __forceinline__ float wsum(float v) {
#pragma unroll
    for (int o = 16; o; o >>= 1) v += __shfl_xor_sync(0xffffffffu, v, o);
    return v;
}

template <int K>
__device__ __forceinline__ void block_atomic_add(float* dst, float* v) {
#pragma unroll
    for (int j = 0; j < K; j++) v[j] = wsum(v[j]);
    __shared__ float bs[K];
    if (threadIdx.x < K) bs[threadIdx.x] = 0.f;
    __syncthreads();
    if ((threadIdx.x & 31) == 0) {
#pragma unroll
        for (int j = 0; j < K; j++) atomicAdd(&bs[j], v[j]);
    }
    __syncthreads();
    if (threadIdx.x < K) atomicAdd(&dst[threadIdx.x], bs[threadIdx.x]);
    __syncthreads();
}

// ---------------- init: pack M into float4 ----------------
__global__ void __launch_bounds__(NT)
k_init(const float* __restrict__ M, float4* __restrict__ Mout) {
    int t = blockIdx.x * NT + threadIdx.x;
    if (t < NV)
        Mout[t] = make_float4(M[3 * t], M[3 * t + 1], M[3 * t + 2], 0.f);
    GDC_LAUNCH;
}

// ---------------- phase A: gather + e-MLP-1 (+ zm), e-stats (2 edges/thread) ----
template <bool DOZ>
__global__ void __launch_bounds__(NT)
k_A(const int* __restrict__ src, const int* __restrict__ dst,
    const float4* __restrict__ M, float4* __restrict__ Mn,
    const float* __restrict__ H, float* __restrict__ statsOut) {
    int t = blockIdx.x * NT + threadIdx.x;
    // ---- prologue (independent of the concurrently-finishing k_C) ----
    if (DOZ) {   // Mn is not touched by k_C(l-1) -> safe pre-wait
        if (t < NV) Mn[t] = make_float4(0.f, 0.f, 0.f, 0.f);
    }
    const int base = 2 * t;           // always < NE (exact grid)
    int2 s2 = __ldg((const int2*)(src + base));
    int2 d2 = __ldg((const int2*)(dst + base));
    float2 hA = __ldg((const float2*)(H + 3 * base));      // H written 2 kernels back
    float2 hB = __ldg((const float2*)(H + 3 * base + 2));
    float2 hC = __ldg((const float2*)(H + 3 * base + 4));
    float hh[6] = {hA.x, hA.y, hB.x, hB.y, hC.x, hC.y};
    float yh[8];
#pragma unroll
    for (int k = 0; k < 2; k++) {
#pragma unroll
        for (int j = 0; j < 4; j++) {
            yh[4*k+j] = cw.we_b1[j]
                      + hh[3*k]*cw.we_w1[6*4+j] + hh[3*k+1]*cw.we_w1[7*4+j] + hh[3*k+2]*cw.we_w1[8*4+j];
        }
    }
    // ---- dependent part: all 4 gathers issued before any consumer ----
    GDC_WAIT;
    float4 mi0 = __ldg(M + d2.x);
    float4 mi1 = __ldg(M + d2.y);
    float4 mj0 = __ldg(M + s2.x);
    float4 mj1 = __ldg(M + s2.y);
    float4 mi[2] = {mi0, mi1};
    float4 mj[2] = {mj0, mj1};
    float acc[8] = {0.f,0.f,0.f,0.f,0.f,0.f,0.f,0.f};
    float zz[6];
#pragma unroll
    for (int k = 0; k < 2; k++) {
        float y[4];
#pragma unroll
        for (int j = 0; j < 4; j++) {
            y[j] = yh[4*k+j]
                 + mi[k].x*cw.we_w1[0*4+j] + mi[k].y*cw.we_w1[1*4+j] + mi[k].z*cw.we_w1[2*4+j]
                 + mj[k].x*cw.we_w1[3*4+j] + mj[k].y*cw.we_w1[4*4+j] + mj[k].z*cw.we_w1[5*4+j];
            acc[j] += y[j];
            acc[4+j] += y[j] * y[j];
        }
        g_Y[base + k] = make_float4(y[0], y[1], y[2], y[3]);
        if (DOZ) {
#pragma unroll
            for (int c = 0; c < 3; c++) {
                zz[3*k+c] = cw.wv_b1[c]
                    + mi[k].x*cw.wv_w1[0*3+c] + mi[k].y*cw.wv_w1[1*3+c] + mi[k].z*cw.wv_w1[2*3+c];
            }
        }
    }
    if (DOZ) {
        float2* Zp = (float2*)(g_Z + 3 * base);
        Zp[0] = make_float2(zz[0], zz[1]);
        Zp[1] = make_float2(zz[2], zz[3]);
        Zp[2] = make_float2(zz[4], zz[5]);
    }
    block_atomic_add<8>(statsOut, acc);
    GDC_LAUNCH;
}

// ---------------- phase B: e-BN -> Hn (-> z, v-stats | head stats) (2 edges/thread) ----
template <bool LAST>
__global__ void __launch_bounds__(NT)
k_B(const float* __restrict__ statsIn, float* __restrict__ statsOut,
    float* __restrict__ headStats) {
    const int t = blockIdx.x * NT + threadIdx.x;
    const int base = 2 * t;
    GDC_WAIT;
    // bulk loads first: overlap their L2 latency with the stats/rsqrt chain
    float4 y4[2];
    y4[0] = __ldg(g_Y + base); y4[1] = __ldg(g_Y + base + 1);
    float zm[6];
    if (!LAST) {
        const float2* Zp = (const float2*)(g_Z + 3 * base);
        float2 a = __ldg(Zp), b = __ldg(Zp + 1), c = __ldg(Zp + 2);
        zm[0]=a.x; zm[1]=a.y; zm[2]=b.x; zm[3]=b.y; zm[4]=c.x; zm[5]=c.y;
    }
    float sc[4], sh[4];
#pragma unroll
    for (int j = 0; j < 4; j++) {
        float m = statsIn[j] * (1.f / NE);
        float v = statsIn[4+j] * (1.f / NE) - m * m;
        float r = rsqrtf(v + BN_EPS);
        sc[j] = r * cw.we_g1[j];
        sh[j] = cw.we_be1[j] - m * sc[j];
    }
    float acc[6] = {0.f,0.f,0.f,0.f,0.f,0.f};
    float hhn[6], zzn[6];
#pragma unroll
    for (int k = 0; k < 2; k++) {
        float tj[4];
        tj[0] = fmaxf(fmaf(y4[k].x, sc[0], sh[0]), 0.f);
        tj[1] = fmaxf(fmaf(y4[k].y, sc[1], sh[1]), 0.f);
        tj[2] = fmaxf(fmaf(y4[k].z, sc[2], sh[2]), 0.f);
        tj[3] = fmaxf(fmaf(y4[k].w, sc[3], sh[3]), 0.f);
        float hn[3];
#pragma unroll
        for (int c = 0; c < 3; c++) {
            hn[c] = cw.we_b2[c]
                  + tj[0]*cw.we_w2[0*3+c] + tj[1]*cw.we_w2[1*3+c]
                  + tj[2]*cw.we_w2[2*3+c] + tj[3]*cw.we_w2[3*3+c];
            hhn[3*k+c] = hn[c];
        }
        if (!LAST) {
#pragma unroll
            for (int c = 0; c < 3; c++) {
                float z = zm[3*k+c]
                        + hn[0]*cw.wv_w1[3*3+c] + hn[1]*cw.wv_w1[4*3+c] + hn[2]*cw.wv_w1[5*3+c];
                zzn[3*k+c] = z;
                acc[c] += z;
                acc[3+c] += z * z;
            }
        } else {
#pragma unroll
            for (int c = 0; c < 3; c++) {
                float yh = cw.ob1[c]
                         + hn[0]*cw.ow1[0*3+c] + hn[1]*cw.ow1[1*3+c] + hn[2]*cw.ow1[2*3+c];
                acc[c] += yh;
                acc[3+c] += yh * yh;
            }
        }
    }
    float2* Hp = (float2*)(g_H + 3 * base);
    Hp[0] = make_float2(hhn[0], hhn[1]);
    Hp[1] = make_float2(hhn[2], hhn[3]);
    Hp[2] = make_float2(hhn[4], hhn[5]);
    if (!LAST) {
        float2* Zo = (float2*)(g_Z + 3 * base);
        Zo[0] = make_float2(zzn[0], zzn[1]);
        Zo[1] = make_float2(zzn[2], zzn[3]);
        Zo[2] = make_float2(zzn[4], zzn[5]);
    }
    if (!LAST) block_atomic_add<6>(statsOut, acc);
    else       block_atomic_add<6>(headStats, acc);
    GDC_LAUNCH;
}

// ---------------- phase C: v-BN -> message -> vec4 scatter-add (2 edges/thread) ----
__global__ void __launch_bounds__(NT)
k_C(const int* __restrict__ dst, float4* __restrict__ Mn,
    const float* __restrict__ statsIn) {
    const int t = blockIdx.x * NT + threadIdx.x;
    const int base = 2 * t;
    int2 d2 = __ldg((const int2*)(dst + base));   // harness input: pre-wait
    GDC_WAIT;
    // bulk Z loads first: overlap L2 latency with stats/rsqrt chain
    const float2* Zp = (const float2*)(g_Z + 3 * base);
    float2 a = __ldg(Zp), b = __ldg(Zp + 1), c2 = __ldg(Zp + 2);
    float sc[3], sh[3];
#pragma unroll
    for (int c = 0; c < 3; c++) {
        float m = statsIn[c] * (1.f / NE);
        float v = statsIn[3+c] * (1.f / NE) - m * m;
        float r = rsqrtf(v + BN_EPS);
        sc[c] = r * cw.wv_g1[c];
        sh[c] = cw.wv_be1[c] - m * sc[c];
    }
    float zz[6] = {a.x, a.y, b.x, b.y, c2.x, c2.y};
    int ids[2] = {d2.x, d2.y};
#pragma unroll
    for (int k = 0; k < 2; k++) {
        float t0 = fmaxf(fmaf(zz[3*k+0], sc[0], sh[0]), 0.f);
        float t1 = fmaxf(fmaf(zz[3*k+1], sc[1], sh[1]), 0.f);
        float t2 = fmaxf(fmaf(zz[3*k+2], sc[2], sh[2]), 0.f);
        float m0 = cw.wv_b2[0] + t0*cw.wv_w2[0] + t1*cw.wv_w2[3] + t2*cw.wv_w2[6];
        float m1 = cw.wv_b2[1] + t0*cw.wv_w2[1] + t1*cw.wv_w2[4] + t2*cw.wv_w2[7];
        float m2 = cw.wv_b2[2] + t0*cw.wv_w2[2] + t1*cw.wv_w2[5] + t2*cw.wv_w2[8];
        float* p = (float*)(Mn + ids[k]);
        asm volatile("red.global.add.v4.f32 [%0], {%1,%2,%3,%4};"
                     :: "l"(p), "f"(m0), "f"(m1), "f"(m2), "f"(0.f) : "memory");
    }
    GDC_LAUNCH;
}

// ---------------- head ----------------
__global__ void __launch_bounds__(NT)
kh_out(const float* __restrict__ statsIn, float* __restrict__ out) {
    const int t = blockIdx.x * NT + threadIdx.x;
    const int base = 4 * t;
    GDC_WAIT;
    if (base < NE) {
        const float4* Hp = (const float4*)(g_H + 3 * base);
        float4 ha = __ldg(Hp), hb = __ldg(Hp + 1), hc = __ldg(Hp + 2);
        float sc[3], sh[3];
#pragma unroll
        for (int c = 0; c < 3; c++) {
            float m = statsIn[c] * (1.f / NE);
            float v = statsIn[3+c] * (1.f / NE) - m * m;
            float r = rsqrtf(v + BN_EPS);
            sc[c] = r * cw.og[c];
            sh[c] = cw.obe[c] - m * sc[c];
        }
        float hh[12] = {ha.x,ha.y,ha.z,ha.w, hb.x,hb.y,hb.z,hb.w, hc.x,hc.y,hc.z,hc.w};
#pragma unroll
        for (int k = 0; k < 4; k++) {
            float tc[3];
#pragma unroll
            for (int c = 0; c < 3; c++) {
                float y = cw.ob1[c]
                        + hh[3*k]*cw.ow1[0*3+c] + hh[3*k+1]*cw.ow1[1*3+c] + hh[3*k+2]*cw.ow1[2*3+c];
                tc[c] = fmaxf(fmaf(y, sc[c], sh[c]), 0.f);
            }
            float l0 = cw.ob2[0] + tc[0]*cw.ow2[0] + tc[1]*cw.ow2[2] + tc[2]*cw.ow2[4];
            float l1 = cw.ob2[1] + tc[0]*cw.ow2[1] + tc[1]*cw.ow2[3] + tc[2]*cw.ow2[5];
            float mx = fmaxf(l0, l1);
            float e0 = __expf(l0 - mx);
            float e1 = __expf(l1 - mx);
            float inv = 1.f / (e0 + e1);
            ((float2*)out)[base + k] = make_float2(e0 * inv, e1 * inv);
        }
    }
    GDC_LAUNCH;
}

// ---------------- PDL launch helper ----------------
template <typename... Args>
static inline void launchPDL(void (*kern)(Args...), int grid, Args... args) {
    cudaLaunchConfig_t cfg = {};
    cfg.gridDim = dim3(grid, 1, 1);
    cfg.blockDim = dim3(NT, 1, 1);
    cfg.dynamicSmemBytes = 0;
    cfg.stream = 0;
    cudaLaunchAttribute attr[1];
    attr[0].id = cudaLaunchAttributeProgrammaticStreamSerialization;
    attr[0].val.programmaticStreamSerializationAllowed = 1;
    cfg.attrs = attr;
    cfg.numAttrs = 1;
    cudaLaunchKernelEx(&cfg, kern, args...);
}

extern "C" void kernel_launch(void* const* d_in, const int* in_sizes, int n_in,
                              void* d_out, int out_size) {
    const float* M  = (const float*)d_in[0];
    const float* H  = (const float*)d_in[1];
    const int*   ei = (const int*)d_in[2];
    const int*   src = ei;
    const int*   dst = ei + NE;

    cudaMemcpyToSymbolAsync(cw, d_in[3],  36*4, offsetof(CW, we_w1), cudaMemcpyDeviceToDevice);
    cudaMemcpyToSymbolAsync(cw, d_in[4],   4*4, offsetof(CW, we_b1), cudaMemcpyDeviceToDevice);
    cudaMemcpyToSymbolAsync(cw, d_in[5],   4*4, offsetof(CW, we_g1), cudaMemcpyDeviceToDevice);
    cudaMemcpyToSymbolAsync(cw, d_in[6],   4*4, offsetof(CW, we_be1), cudaMemcpyDeviceToDevice);
    cudaMemcpyToSymbolAsync(cw, d_in[7],  12*4, offsetof(CW, we_w2), cudaMemcpyDeviceToDevice);
    cudaMemcpyToSymbolAsync(cw, d_in[8],   3*4, offsetof(CW, we_b2), cudaMemcpyDeviceToDevice);
    cudaMemcpyToSymbolAsync(cw, d_in[9],  18*4, offsetof(CW, wv_w1), cudaMemcpyDeviceToDevice);
    cudaMemcpyToSymbolAsync(cw, d_in[10],  3*4, offsetof(CW, wv_b1), cudaMemcpyDeviceToDevice);
    cudaMemcpyToSymbolAsync(cw, d_in[11],  3*4, offsetof(CW, wv_g1), cudaMemcpyDeviceToDevice);
    cudaMemcpyToSymbolAsync(cw, d_in[12],  3*4, offsetof(CW, wv_be1), cudaMemcpyDeviceToDevice);
    cudaMemcpyToSymbolAsync(cw, d_in[13],  9*4, offsetof(CW, wv_w2), cudaMemcpyDeviceToDevice);
    cudaMemcpyToSymbolAsync(cw, d_in[14],  3*4, offsetof(CW, wv_b2), cudaMemcpyDeviceToDevice);
    cudaMemcpyToSymbolAsync(cw, d_in[15],  9*4, offsetof(CW, ow1), cudaMemcpyDeviceToDevice);
    cudaMemcpyToSymbolAsync(cw, d_in[16],  3*4, offsetof(CW, ob1), cudaMemcpyDeviceToDevice);
    cudaMemcpyToSymbolAsync(cw, d_in[17],  3*4, offsetof(CW, og), cudaMemcpyDeviceToDevice);
    cudaMemcpyToSymbolAsync(cw, d_in[18],  3*4, offsetof(CW, obe), cudaMemcpyDeviceToDevice);
    cudaMemcpyToSymbolAsync(cw, d_in[19],  6*4, offsetof(CW, ow2), cudaMemcpyDeviceToDevice);
    cudaMemcpyToSymbolAsync(cw, d_in[20],  2*4, offsetof(CW, ob2), cudaMemcpyDeviceToDevice);

    float4 *gM0, *gM1; float* gStats; float* gH; void* p;
    cudaGetSymbolAddress(&p, g_M);     gM0 = (float4*)p; gM1 = gM0 + NV;
    cudaGetSymbolAddress(&p, g_stats); gStats = (float*)p;
    cudaGetSymbolAddress(&p, g_H);     gH = (float*)p;
    cudaMemsetAsync(gStats, 0, sizeof(float) * 22 * 16);

    launchPDL(k_init, NBLKI, M, gM0);

    for (int l = 0; l < NLAYER; l++) {
        float4* Mc = (l & 1) ? gM1 : gM0;
        float4* Mn = (l & 1) ? gM0 : gM1;
        const float* Hread = (l == 0) ? H : (const float*)gH;
        float* se = gStats + l * 16;
        float* sv = se + 8;
        if (l == NLAYER - 1) {
            launchPDL(k_A<false>, NBLK2, src, dst, (const float4*)Mc, Mn, Hread, se);
            launchPDL(k_B<true>, NBLK2, (const float*)se, sv, gStats + 20 * 16);
        } else {
            launchPDL(k_A<true>, NBLK2, src, dst, (const float4*)Mc, Mn, Hread, se);
            launchPDL(k_B<false>, NBLK2, (const float*)se, sv, gStats + 20 * 16);
            launchPDL(k_C, NBLK2, dst, Mn, (const float*)sv);
        }
    }
    launchPDL(kh_out, NBLK4, (const float*)(gStats + 20 * 16), (float*)d_out);
}

// round 13
// speedup vs baseline: 1.0682x; 1.0682x over previous
#include <cuda_runtime.h>
#include <cstddef>

#define NE 1600000
#define NV 100000
#define NLAYER 20
#define BN_EPS 1e-5f
#define NT 256
#define NBLK2 3125              // NE/2 / 256 exactly -> no bounds checks
#define NBLK4 1563              // ceil(NE/4 / 256) for head
#define NBLKI 391               // ceil(NV / 256) for init

#define GDC_WAIT   asm volatile("griddepcontrol.wait;" ::: "memory")
#define GDC_LAUNCH asm volatile("griddepcontrol.launch_dependents;" ::: "memory")

// ---------------- constant weights (128 floats, packed) ----------------
struct CW {
    float we_w1[36], we_b1[4], we_g1[4], we_be1[4], we_w2[12], we_b2[3];
    float wv_w1[18], wv_b1[3], wv_g1[3], wv_be1[3], wv_w2[9], wv_b2[3];
    float ow1[9], ob1[3], og[3], obe[3], ow2[6], ob2[2];
};
__constant__ CW cw;

// ---------------- persistent device state ----------------
__device__ float4 g_M[2][NV];     // node features, double buffered
__device__ float  g_H[NE * 3];    // edge features
__device__ float4 g_Y[NE];        // phase-A pre-BN e-MLP output
__device__ float  g_Z[NE * 3];    // phase-A: mi-part of z ; phase-B: full z
__device__ float  g_stats[22 * 16];
__device__ float  g_stage[128];   // staging for the single cw memcpy

__device__ __forceinline__ float wsum(float v) {
#pragma unroll
    for (int o = 16; o; o >>= 1) v += __shfl_xor_sync(0xffffffffu, v, o);
    return v;
}

template <int K>
__device__ __forceinline__ void block_atomic_add(float* dst, float* v) {
#pragma unroll
    for (int j = 0; j < K; j++) v[j] = wsum(v[j]);
    __shared__ float bs[K];
    if (threadIdx.x < K) bs[threadIdx.x] = 0.f;
    __syncthreads();
    if ((threadIdx.x & 31) == 0) {
#pragma unroll
        for (int j = 0; j < K; j++) atomicAdd(&bs[j], v[j]);
    }
    __syncthreads();
    if (threadIdx.x < K) atomicAdd(&dst[threadIdx.x], bs[threadIdx.x]);
    __syncthreads();
}

// ---------------- pack: 18 weight buffers -> g_stage; zero stats (1 node) ----
__global__ void k_pack(const float* w0, const float* w1, const float* w2,
                       const float* w3, const float* w4, const float* w5,
                       const float* w6, const float* w7, const float* w8,
                       const float* w9, const float* w10, const float* w11,
                       const float* w12, const float* w13, const float* w14,
                       const float* w15, const float* w16, const float* w17) {
    int tid = threadIdx.x;
    g_stats[tid] = 0.f;
    if (tid + 256 < 22 * 16) g_stats[tid + 256] = 0.f;
    if (tid < 36) g_stage[0   + tid] = __ldg(w0 + tid);   // we_w1
    if (tid < 4)  g_stage[36  + tid] = __ldg(w1 + tid);   // we_b1
    if (tid < 4)  g_stage[40  + tid] = __ldg(w2 + tid);   // we_g1
    if (tid < 4)  g_stage[44  + tid] = __ldg(w3 + tid);   // we_be1
    if (tid < 12) g_stage[48  + tid] = __ldg(w4 + tid);   // we_w2
    if (tid < 3)  g_stage[60  + tid] = __ldg(w5 + tid);   // we_b2
    if (tid < 18) g_stage[63  + tid] = __ldg(w6 + tid);   // wv_w1
    if (tid < 3)  g_stage[81  + tid] = __ldg(w7 + tid);   // wv_b1
    if (tid < 3)  g_stage[84  + tid] = __ldg(w8 + tid);   // wv_g1
    if (tid < 3)  g_stage[87  + tid] = __ldg(w9 + tid);   // wv_be1
    if (tid < 9)  g_stage[90  + tid] = __ldg(w10 + tid);  // wv_w2
    if (tid < 3)  g_stage[99  + tid] = __ldg(w11 + tid);  // wv_b2
    if (tid < 9)  g_stage[102 + tid] = __ldg(w12 + tid);  // ow1
    if (tid < 3)  g_stage[111 + tid] = __ldg(w13 + tid);  // ob1
    if (tid < 3)  g_stage[114 + tid] = __ldg(w14 + tid);  // og
    if (tid < 3)  g_stage[117 + tid] = __ldg(w15 + tid);  // obe
    if (tid < 6)  g_stage[120 + tid] = __ldg(w16 + tid);  // ow2
    if (tid < 2)  g_stage[126 + tid] = __ldg(w17 + tid);  // ob2
}

// ---------------- init: pack M into float4 ----------------
__global__ void __launch_bounds__(NT)
k_init(const float* __restrict__ M, float4* __restrict__ Mout) {
    int t = blockIdx.x * NT + threadIdx.x;
    if (t < NV)
        Mout[t] = make_float4(M[3 * t], M[3 * t + 1], M[3 * t + 2], 0.f);
    GDC_LAUNCH;
}

// ---------------- phase A: gather + e-MLP-1 (+ zm), e-stats (2 edges/thread) ----
template <bool DOZ>
__global__ void __launch_bounds__(NT)
k_A(const int* __restrict__ src, const int* __restrict__ dst,
    const float4* __restrict__ M, float4* __restrict__ Mn,
    const float* __restrict__ H, float* __restrict__ statsOut) {
    int t = blockIdx.x * NT + threadIdx.x;
    // ---- prologue (independent of the concurrently-finishing k_C) ----
    if (DOZ) {   // Mn is not touched by k_C(l-1) -> safe pre-wait
        if (t < NV) Mn[t] = make_float4(0.f, 0.f, 0.f, 0.f);
    }
    const int base = 2 * t;           // always < NE (exact grid)
    int2 s2 = __ldg((const int2*)(src + base));
    int2 d2 = __ldg((const int2*)(dst + base));
    float2 hA = __ldg((const float2*)(H + 3 * base));      // H written 2 kernels back
    float2 hB = __ldg((const float2*)(H + 3 * base + 2));
    float2 hC = __ldg((const float2*)(H + 3 * base + 4));
    float hh[6] = {hA.x, hA.y, hB.x, hB.y, hC.x, hC.y};
    float yh[8];
#pragma unroll
    for (int k = 0; k < 2; k++) {
#pragma unroll
        for (int j = 0; j < 4; j++) {
            yh[4*k+j] = cw.we_b1[j]
                      + hh[3*k]*cw.we_w1[6*4+j] + hh[3*k+1]*cw.we_w1[7*4+j] + hh[3*k+2]*cw.we_w1[8*4+j];
        }
    }
    // ---- dependent part: M gathers ----
    GDC_WAIT;
    float4 mi[2], mj[2];
    mi[0] = __ldg(M + d2.x); mi[1] = __ldg(M + d2.y);
    mj[0] = __ldg(M + s2.x); mj[1] = __ldg(M + s2.y);
    float acc[8] = {0.f,0.f,0.f,0.f,0.f,0.f,0.f,0.f};
    float zz[6];
#pragma unroll
    for (int k = 0; k < 2; k++) {
        float y[4];
#pragma unroll
        for (int j = 0; j < 4; j++) {
            y[j] = yh[4*k+j]
                 + mi[k].x*cw.we_w1[0*4+j] + mi[k].y*cw.we_w1[1*4+j] + mi[k].z*cw.we_w1[2*4+j]
                 + mj[k].x*cw.we_w1[3*4+j] + mj[k].y*cw.we_w1[4*4+j] + mj[k].z*cw.we_w1[5*4+j];
            acc[j] += y[j];
            acc[4+j] += y[j] * y[j];
        }
        g_Y[base + k] = make_float4(y[0], y[1], y[2], y[3]);
        if (DOZ) {
#pragma unroll
            for (int c = 0; c < 3; c++) {
                zz[3*k+c] = cw.wv_b1[c]
                    + mi[k].x*cw.wv_w1[0*3+c] + mi[k].y*cw.wv_w1[1*3+c] + mi[k].z*cw.wv_w1[2*3+c];
            }
        }
    }
    if (DOZ) {
        float2* Zp = (float2*)(g_Z + 3 * base);
        Zp[0] = make_float2(zz[0], zz[1]);
        Zp[1] = make_float2(zz[2], zz[3]);
        Zp[2] = make_float2(zz[4], zz[5]);
    }
    block_atomic_add<8>(statsOut, acc);
    GDC_LAUNCH;
}

// ---------------- phase B: e-BN -> Hn (-> z, v-stats | head stats) (2 edges/thread) ----
template <bool LAST>
__global__ void __launch_bounds__(NT)
k_B(const float* __restrict__ statsIn, float* __restrict__ statsOut,
    float* __restrict__ headStats) {
    GDC_WAIT;
    float sc[4], sh[4];
#pragma unroll
    for (int j = 0; j < 4; j++) {
        float m = statsIn[j] * (1.f / NE);
        float v = statsIn[4+j] * (1.f / NE) - m * m;
        float r = rsqrtf(v + BN_EPS);
        sc[j] = r * cw.we_g1[j];
        sh[j] = cw.we_be1[j] - m * sc[j];
    }
    const int t = blockIdx.x * NT + threadIdx.x;
    const int base = 2 * t;
    float4 y4[2];
    y4[0] = __ldg(g_Y + base); y4[1] = __ldg(g_Y + base + 1);
    float zm[6];
    if (!LAST) {
        const float2* Zp = (const float2*)(g_Z + 3 * base);
        float2 a = __ldg(Zp), b = __ldg(Zp + 1), c = __ldg(Zp + 2);
        zm[0]=a.x; zm[1]=a.y; zm[2]=b.x; zm[3]=b.y; zm[4]=c.x; zm[5]=c.y;
    }
    float acc[6] = {0.f,0.f,0.f,0.f,0.f,0.f};
    float hhn[6], zzn[6];
#pragma unroll
    for (int k = 0; k < 2; k++) {
        float tj[4];
        tj[0] = fmaxf(fmaf(y4[k].x, sc[0], sh[0]), 0.f);
        tj[1] = fmaxf(fmaf(y4[k].y, sc[1], sh[1]), 0.f);
        tj[2] = fmaxf(fmaf(y4[k].z, sc[2], sh[2]), 0.f);
        tj[3] = fmaxf(fmaf(y4[k].w, sc[3], sh[3]), 0.f);
        float hn[3];
#pragma unroll
        for (int c = 0; c < 3; c++) {
            hn[c] = cw.we_b2[c]
                  + tj[0]*cw.we_w2[0*3+c] + tj[1]*cw.we_w2[1*3+c]
                  + tj[2]*cw.we_w2[2*3+c] + tj[3]*cw.we_w2[3*3+c];
            hhn[3*k+c] = hn[c];
        }
        if (!LAST) {
#pragma unroll
            for (int c = 0; c < 3; c++) {
                float z = zm[3*k+c]
                        + hn[0]*cw.wv_w1[3*3+c] + hn[1]*cw.wv_w1[4*3+c] + hn[2]*cw.wv_w1[5*3+c];
                zzn[3*k+c] = z;
                acc[c] += z;
                acc[3+c] += z * z;
            }
        } else {
#pragma unroll
            for (int c = 0; c < 3; c++) {
                float yh = cw.ob1[c]
                         + hn[0]*cw.ow1[0*3+c] + hn[1]*cw.ow1[1*3+c] + hn[2]*cw.ow1[2*3+c];
                acc[c] += yh;
                acc[3+c] += yh * yh;
            }
        }
    }
    float2* Hp = (float2*)(g_H + 3 * base);
    Hp[0] = make_float2(hhn[0], hhn[1]);
    Hp[1] = make_float2(hhn[2], hhn[3]);
    Hp[2] = make_float2(hhn[4], hhn[5]);
    if (!LAST) {
        float2* Zo = (float2*)(g_Z + 3 * base);
        Zo[0] = make_float2(zzn[0], zzn[1]);
        Zo[1] = make_float2(zzn[2], zzn[3]);
        Zo[2] = make_float2(zzn[4], zzn[5]);
    }
    if (!LAST) block_atomic_add<6>(statsOut, acc);
    else       block_atomic_add<6>(headStats, acc);
    GDC_LAUNCH;
}

// ---------------- phase C: v-BN -> message -> vec4 scatter-add (2 edges/thread) ----
__global__ void __launch_bounds__(NT)
k_C(const int* __restrict__ dst, float4* __restrict__ Mn,
    const float* __restrict__ statsIn) {
    const int t = blockIdx.x * NT + threadIdx.x;
    const int base = 2 * t;
    int2 d2 = __ldg((const int2*)(dst + base));   // harness input: pre-wait
    GDC_WAIT;
    float sc[3], sh[3];
#pragma unroll
    for (int c = 0; c < 3; c++) {
        float m = statsIn[c] * (1.f / NE);
        float v = statsIn[3+c] * (1.f / NE) - m * m;
        float r = rsqrtf(v + BN_EPS);
        sc[c] = r * cw.wv_g1[c];
        sh[c] = cw.wv_be1[c] - m * sc[c];
    }
    const float2* Zp = (const float2*)(g_Z + 3 * base);
    float2 a = __ldg(Zp), b = __ldg(Zp + 1), c2 = __ldg(Zp + 2);
    float zz[6] = {a.x, a.y, b.x, b.y, c2.x, c2.y};
    int ids[2] = {d2.x, d2.y};
#pragma unroll
    for (int k = 0; k < 2; k++) {
        float t0 = fmaxf(fmaf(zz[3*k+0], sc[0], sh[0]), 0.f);
        float t1 = fmaxf(fmaf(zz[3*k+1], sc[1], sh[1]), 0.f);
        float t2 = fmaxf(fmaf(zz[3*k+2], sc[2], sh[2]), 0.f);
        float m0 = cw.wv_b2[0] + t0*cw.wv_w2[0] + t1*cw.wv_w2[3] + t2*cw.wv_w2[6];
        float m1 = cw.wv_b2[1] + t0*cw.wv_w2[1] + t1*cw.wv_w2[4] + t2*cw.wv_w2[7];
        float m2 = cw.wv_b2[2] + t0*cw.wv_w2[2] + t1*cw.wv_w2[5] + t2*cw.wv_w2[8];
        float* p = (float*)(Mn + ids[k]);
        asm volatile("red.global.add.v4.f32 [%0], {%1,%2,%3,%4};"
                     :: "l"(p), "f"(m0), "f"(m1), "f"(m2), "f"(0.f) : "memory");
    }
    GDC_LAUNCH;
}

// ---------------- head ----------------
__global__ void __launch_bounds__(NT)
kh_out(const float* __restrict__ statsIn, float* __restrict__ out) {
    GDC_WAIT;
    float sc[3], sh[3];
#pragma unroll
    for (int c = 0; c < 3; c++) {
        float m = statsIn[c] * (1.f / NE);
        float v = statsIn[3+c] * (1.f / NE) - m * m;
        float r = rsqrtf(v + BN_EPS);
        sc[c] = r * cw.og[c];
        sh[c] = cw.obe[c] - m * sc[c];
    }
    int t = blockIdx.x * NT + threadIdx.x;
    int base = 4 * t;
    if (base < NE) {
        const float4* Hp = (const float4*)(g_H + 3 * base);
        float4 ha = __ldg(Hp), hb = __ldg(Hp + 1), hc = __ldg(Hp + 2);
        float hh[12] = {ha.x,ha.y,ha.z,ha.w, hb.x,hb.y,hb.z,hb.w, hc.x,hc.y,hc.z,hc.w};
#pragma unroll
        for (int k = 0; k < 4; k++) {
            float tc[3];
#pragma unroll
            for (int c = 0; c < 3; c++) {
                float y = cw.ob1[c]
                        + hh[3*k]*cw.ow1[0*3+c] + hh[3*k+1]*cw.ow1[1*3+c] + hh[3*k+2]*cw.ow1[2*3+c];
                tc[c] = fmaxf(fmaf(y, sc[c], sh[c]), 0.f);
            }
            float l0 = cw.ob2[0] + tc[0]*cw.ow2[0] + tc[1]*cw.ow2[2] + tc[2]*cw.ow2[4];
            float l1 = cw.ob2[1] + tc[0]*cw.ow2[1] + tc[1]*cw.ow2[3] + tc[2]*cw.ow2[5];
            float mx = fmaxf(l0, l1);
            float e0 = __expf(l0 - mx);
            float e1 = __expf(l1 - mx);
            float inv = 1.f / (e0 + e1);
            ((float2*)out)[base + k] = make_float2(e0 * inv, e1 * inv);
        }
    }
    GDC_LAUNCH;
}

// ---------------- PDL launch helper ----------------
template <typename... Args>
static inline void launchPDL(void (*kern)(Args...), int grid, Args... args) {
    cudaLaunchConfig_t cfg = {};
    cfg.gridDim = dim3(grid, 1, 1);
    cfg.blockDim = dim3(NT, 1, 1);
    cfg.dynamicSmemBytes = 0;
    cfg.stream = 0;
    cudaLaunchAttribute attr[1];
    attr[0].id = cudaLaunchAttributeProgrammaticStreamSerialization;
    attr[0].val.programmaticStreamSerializationAllowed = 1;
    cfg.attrs = attr;
    cfg.numAttrs = 1;
    cudaLaunchKernelEx(&cfg, kern, args...);
}

extern "C" void kernel_launch(void* const* d_in, const int* in_sizes, int n_in,
                              void* d_out, int out_size) {
    const float* M  = (const float*)d_in[0];
    const float* H  = (const float*)d_in[1];
    const int*   ei = (const int*)d_in[2];
    const int*   src = ei;
    const int*   dst = ei + NE;

    float4 *gM0, *gM1; float *gStats, *gH, *gStage; void* p;
    cudaGetSymbolAddress(&p, g_M);     gM0 = (float4*)p; gM1 = gM0 + NV;
    cudaGetSymbolAddress(&p, g_stats); gStats = (float*)p;
    cudaGetSymbolAddress(&p, g_H);     gH = (float*)p;
    cudaGetSymbolAddress(&p, g_stage); gStage = (float*)p;

    // 1 kernel node: gather all weights into staging + zero stats
    k_pack<<<1, 256>>>(
        (const float*)d_in[3],  (const float*)d_in[4],  (const float*)d_in[5],
        (const float*)d_in[6],  (const float*)d_in[7],  (const float*)d_in[8],
        (const float*)d_in[9],  (const float*)d_in[10], (const float*)d_in[11],
        (const float*)d_in[12], (const float*)d_in[13], (const float*)d_in[14],
        (const float*)d_in[15], (const float*)d_in[16], (const float*)d_in[17],
        (const float*)d_in[18], (const float*)d_in[19], (const float*)d_in[20]);

    // 1 memcpy node: staging -> __constant__ cw (full stream serialization here)
    cudaMemcpyToSymbolAsync(cw, gStage, 128 * sizeof(float), 0, cudaMemcpyDeviceToDevice);

    launchPDL(k_init, NBLKI, M, gM0);

    for (int l = 0; l < NLAYER; l++) {
        float4* Mc = (l & 1) ? gM1 : gM0;
        float4* Mn = (l & 1) ? gM0 : gM1;
        const float* Hread = (l == 0) ? H : (const float*)gH;
        float* se = gStats + l * 16;
        float* sv = se + 8;
        if (l == NLAYER - 1) {
            launchPDL(k_A<false>, NBLK2, src, dst, (const float4*)Mc, Mn, Hread, se);
            launchPDL(k_B<true>, NBLK2, (const float*)se, sv, gStats + 20 * 16);
        } else {
            launchPDL(k_A<true>, NBLK2, src, dst, (const float4*)Mc, Mn, Hread, se);
            launchPDL(k_B<false>, NBLK2, (const float*)se, sv, gStats + 20 * 16);
            launchPDL(k_C, NBLK2, dst, Mn, (const float*)sv);
        }
    }
    launchPDL(kh_out, NBLK4, (const float*)(gStats + 20 * 16), (float*)d_out);
}